// round 3
// baseline (speedup 1.0000x reference)
#include <cuda_runtime.h>
#include <cuda_bf16.h>
#include <cstdio>

// Problem constants
#define B_   4
#define C_   256
#define CK_  448
#define N_   4096
#define NEGV (-1e15f)

// ---------------- scratch (device globals; no runtime allocation) ----------------
__device__ float g_Q [(size_t)B_ * N_ * CK_];   // [b][n][ck]   (Fq)
__device__ float g_KT[(size_t)B_ * CK_ * N_];   // [b][ck][n]   (G, key-transposed)
__device__ float g_V [(size_t)B_ * N_ * C_];    // [b][n][c]    (Hv)
__device__ float g_cmean[B_ * C_];
__device__ float g_crstd[B_ * C_];

// ---------------- packed f32x2 helpers (Blackwell FFMA2 path) ----------------
typedef unsigned long long u64v;
__device__ __forceinline__ u64v pk2(float x, float y) {
    u64v r; asm("mov.b64 %0, {%1, %2};" : "=l"(r) : "f"(x), "f"(y)); return r;
}
__device__ __forceinline__ void upk2(u64v v, float& x, float& y) {
    asm("mov.b64 {%0, %1}, %2;" : "=f"(x), "=f"(y) : "l"(v));
}
__device__ __forceinline__ u64v ffma2(u64v a, u64v b, u64v c) {
    u64v d; asm("fma.rn.f32x2 %0, %1, %2, %3;" : "=l"(d) : "l"(a), "l"(b), "l"(c)); return d;
}
__device__ __forceinline__ u64v fmul2(u64v a, u64v b) {
    u64v d; asm("mul.rn.f32x2 %0, %1, %2;" : "=l"(d) : "l"(a), "l"(b)); return d;
}

// ---------------- kernel 1: per-(b,c) mean / rstd of content (mvn stats) ----------------
__global__ __launch_bounds__(256) void stats_kernel(const float* __restrict__ content) {
    int bc = blockIdx.x;                    // 0..B_*C_-1
    const float4* x = (const float4*)(content + (size_t)bc * N_);
    int tid = threadIdx.x;
    float s = 0.f, q = 0.f;
    for (int i = tid; i < N_ / 4; i += 256) {
        float4 v = x[i];
        s += v.x + v.y + v.z + v.w;
        q += v.x * v.x + v.y * v.y + v.z * v.z + v.w * v.w;
    }
    // warp reduce
    #pragma unroll
    for (int off = 16; off; off >>= 1) {
        s += __shfl_xor_sync(0xffffffffu, s, off);
        q += __shfl_xor_sync(0xffffffffu, q, off);
    }
    __shared__ float ss[8], qq[8];
    int wid = tid >> 5, lane = tid & 31;
    if (lane == 0) { ss[wid] = s; qq[wid] = q; }
    __syncthreads();
    if (tid == 0) {
        float S = 0.f, Q = 0.f;
        #pragma unroll
        for (int i = 0; i < 8; i++) { S += ss[i]; Q += qq[i]; }
        float mean = S / (float)N_;
        float var  = (Q - (float)N_ * mean * mean) / (float)(N_ - 1);   // unbiased (ddof=1)
        g_cmean[bc] = mean;
        g_crstd[bc] = rsqrtf(var + 1e-5f);
    }
}

// ---------------- kernel 2: 1x1-conv projection GEMM ----------------
// Y[b,n,o] = sum_c X[b,c,n] * W[o,c] + bias[o]
// TRANS=false: Y stored [b][n][o] (stride Cout). TRANS=true: Y stored [b][o][n] (stride N_).
template<int CIN, bool TRANS>
__global__ __launch_bounds__(256) void proj_kernel(const float* __restrict__ X,
                                                   const float* __restrict__ W,
                                                   const float* __restrict__ bias,
                                                   float* __restrict__ Y, int Cout) {
    __shared__ float Xs[32 * 64];   // [cc][n]
    __shared__ float Ws[32 * 64];   // [cc][o]  (transposed on load)
    int b  = blockIdx.z;
    int n0 = blockIdx.x * 64;
    int o0 = blockIdx.y * 64;
    int tid = threadIdx.x;
    int tx = tid & 15;              // -> o group (4 o's)
    int ty = tid >> 4;              // -> n group (4 n's)

    u64v acc2[2][4];                // [n-pair][o]  pairs over n: (0,1),(2,3)
    #pragma unroll
    for (int p = 0; p < 2; p++)
        #pragma unroll
        for (int j = 0; j < 4; j++) acc2[p][j] = 0ull;

    for (int c0 = 0; c0 < CIN; c0 += 32) {
        __syncthreads();
        // X tile: 32c x 64n, contiguous along n
        for (int e = tid; e < 512; e += 256) {
            int cc = e >> 4, nn = (e & 15) << 2;
            *(float4*)&Xs[cc * 64 + nn] =
                *(const float4*)&X[((size_t)(b * CIN + c0 + cc)) * N_ + n0 + nn];
        }
        // W tile transposed: read W[o][c] along c, scatter to Ws[c][o]
        for (int e = tid; e < 512; e += 256) {
            int oo = e >> 3, c4 = (e & 7) << 2;
            float4 v = *(const float4*)&W[(size_t)(o0 + oo) * CIN + c0 + c4];
            Ws[(c4 + 0) * 64 + oo] = v.x;
            Ws[(c4 + 1) * 64 + oo] = v.y;
            Ws[(c4 + 2) * 64 + oo] = v.z;
            Ws[(c4 + 3) * 64 + oo] = v.w;
        }
        __syncthreads();
        #pragma unroll 8
        for (int cc = 0; cc < 32; cc++) {
            u64v xp0 = *(const u64v*)&Xs[cc * 64 + ty * 4];
            u64v xp1 = *(const u64v*)&Xs[cc * 64 + ty * 4 + 2];
            float4 w4 = *(const float4*)&Ws[cc * 64 + tx * 4];
            u64v w0 = pk2(w4.x, w4.x), w1 = pk2(w4.y, w4.y);
            u64v w2 = pk2(w4.z, w4.z), w3 = pk2(w4.w, w4.w);
            acc2[0][0] = ffma2(xp0, w0, acc2[0][0]);
            acc2[0][1] = ffma2(xp0, w1, acc2[0][1]);
            acc2[0][2] = ffma2(xp0, w2, acc2[0][2]);
            acc2[0][3] = ffma2(xp0, w3, acc2[0][3]);
            acc2[1][0] = ffma2(xp1, w0, acc2[1][0]);
            acc2[1][1] = ffma2(xp1, w1, acc2[1][1]);
            acc2[1][2] = ffma2(xp1, w2, acc2[1][2]);
            acc2[1][3] = ffma2(xp1, w3, acc2[1][3]);
        }
    }
    float a[4][4];
    #pragma unroll
    for (int p = 0; p < 2; p++)
        #pragma unroll
        for (int j = 0; j < 4; j++) upk2(acc2[p][j], a[2 * p][j], a[2 * p + 1][j]);
    float4 bo = *(const float4*)&bias[o0 + tx * 4];
    float bb[4] = {bo.x, bo.y, bo.z, bo.w};
    if (!TRANS) {
        #pragma unroll
        for (int i = 0; i < 4; i++) {
            float4 st = {a[i][0] + bb[0], a[i][1] + bb[1], a[i][2] + bb[2], a[i][3] + bb[3]};
            *(float4*)&Y[((size_t)(b * N_) + n0 + ty * 4 + i) * Cout + o0 + tx * 4] = st;
        }
    } else {
        #pragma unroll
        for (int j = 0; j < 4; j++) {
            float4 st = {a[0][j] + bb[j], a[1][j] + bb[j], a[2][j] + bb[j], a[3][j] + bb[j]};
            *(float4*)&Y[((size_t)(b * Cout) + o0 + tx * 4 + j) * N_ + n0 + ty * 4] = st;
        }
    }
}

// ---------------- kernel 3: fused masked flash-attention + epilogue ----------------
// CTA: batch b, 32 query rows. Loop over 32 key tiles of 128 keys.
// SMEM float offsets
#define QS_OFF  0            // [32][449]
#define KS_OFF  14368        // [64][128]   (K^T chunk: [ck][key])
#define VS_OFF  22560        // [128][64]
#define PS_OFF  30752        // [32][128]
#define SMK_OFF 34848        // [128] ints
#define SMEM_FLOATS 34976
#define SMEM_BYTES  (SMEM_FLOATS * 4)

__global__ __launch_bounds__(256, 1) void attn_kernel(const float* __restrict__ content,
                                                      const int* __restrict__ cmask,
                                                      const int* __restrict__ smask,
                                                      float* __restrict__ out) {
    extern __shared__ float sm[];
    float* Qs = sm + QS_OFF;
    float* Ks = sm + KS_OFF;
    float* Vs = sm + VS_OFF;
    float* Ps = sm + PS_OFF;
    int*   smk = (int*)(sm + SMK_OFF);

    int b  = blockIdx.y;
    int n0 = blockIdx.x * 32;
    int tid = threadIdx.x;
    int tx = tid & 15;       // key-col group (S) / channel group (PV)
    int ty = tid >> 4;       // owns query rows ty and ty+16

    // load Q tile [32][448] -> Qs stride 449 (conflict-free scalar reads)
    for (int e = tid; e < 32 * 112; e += 256) {
        int r = e / 112, o4 = (e % 112) * 4;
        float4 v = *(const float4*)&g_Q[((size_t)b * N_ + n0 + r) * CK_ + o4];
        float* dst = &Qs[r * 449 + o4];
        dst[0] = v.x; dst[1] = v.y; dst[2] = v.z; dst[3] = v.w;
    }
    int cmr0 = cmask[b * N_ + n0 + ty]      != 0;
    int cmr1 = cmask[b * N_ + n0 + ty + 16] != 0;

    float mrow[2] = {-3.4e38f, -3.4e38f};
    float lrow[2] = {0.f, 0.f};
    u64v accM[2][8], accQ[2][8];   // [row][vc*2+h]: packed channel pairs; mean-acc & m2-acc
    #pragma unroll
    for (int r = 0; r < 2; r++)
        #pragma unroll
        for (int h = 0; h < 8; h++) { accM[r][h] = 0ull; accQ[r][h] = 0ull; }

    for (int kt = 0; kt < 32; kt++) {
        int k0 = kt * 128;
        if (tid < 128) smk[tid] = (smask[b * N_ + k0 + tid] == 0);

        // ---- S = Q K^T over 7 chunks of 64 ck ----
        u64v s2[2][4];
        #pragma unroll
        for (int r = 0; r < 2; r++)
            #pragma unroll
            for (int g = 0; g < 4; g++) s2[r][g] = 0ull;

        for (int ckc = 0; ckc < 7; ckc++) {
            __syncthreads();
            for (int e = tid; e < 64 * 32; e += 256) {
                int cc = e >> 5, k4 = (e & 31) << 2;
                *(float4*)&Ks[cc * 128 + k4] =
                    *(const float4*)&g_KT[((size_t)b * CK_ + ckc * 64 + cc) * N_ + k0 + k4];
            }
            __syncthreads();
            const float* qp0 = &Qs[ty * 449 + ckc * 64];
            const float* qp1 = &Qs[(ty + 16) * 449 + ckc * 64];
            #pragma unroll 8
            for (int cc = 0; cc < 64; cc++) {
                u64v q0 = pk2(qp0[cc], qp0[cc]);
                u64v q1 = pk2(qp1[cc], qp1[cc]);
                const u64v* krow = (const u64v*)&Ks[cc * 128];
                u64v ka = krow[tx * 2], kb = krow[tx * 2 + 1];
                u64v kc = krow[32 + tx * 2], kd = krow[32 + tx * 2 + 1];
                s2[0][0] = ffma2(q0, ka, s2[0][0]);
                s2[0][1] = ffma2(q0, kb, s2[0][1]);
                s2[0][2] = ffma2(q0, kc, s2[0][2]);
                s2[0][3] = ffma2(q0, kd, s2[0][3]);
                s2[1][0] = ffma2(q1, ka, s2[1][0]);
                s2[1][1] = ffma2(q1, kb, s2[1][1]);
                s2[1][2] = ffma2(q1, kc, s2[1][2]);
                s2[1][3] = ffma2(q1, kd, s2[1][3]);
            }
        }

        // ---- mask + online softmax (rows ty, ty+16; 16 lanes per row) ----
        float s[2][8];
        #pragma unroll
        for (int r = 0; r < 2; r++)
            #pragma unroll
            for (int g = 0; g < 4; g++) upk2(s2[r][g], s[r][2 * g], s[r][2 * g + 1]);

        #pragma unroll
        for (int r = 0; r < 2; r++) {
            int cm = (r == 0) ? cmr0 : cmr1;
            if (cm) {
                #pragma unroll
                for (int j = 0; j < 8; j++) {
                    int col = (j < 4) ? (tx * 4 + j) : (64 + tx * 4 + j - 4);
                    if (smk[col]) s[r][j] = NEGV;
                }
            }
            float mloc = s[r][0];
            #pragma unroll
            for (int j = 1; j < 8; j++) mloc = fmaxf(mloc, s[r][j]);
            #pragma unroll
            for (int off = 8; off; off >>= 1)
                mloc = fmaxf(mloc, __shfl_xor_sync(0xffffffffu, mloc, off));
            float mnew = fmaxf(mrow[r], mloc);
            float scf  = __expf(mrow[r] - mnew);
            mrow[r] = mnew;
            float ps = 0.f, p[8];
            #pragma unroll
            for (int j = 0; j < 8; j++) { p[j] = __expf(s[r][j] - mnew); ps += p[j]; }
            lrow[r] = lrow[r] * scf + ps;
            int rr = (r == 0) ? ty : (ty + 16);
            #pragma unroll
            for (int j = 0; j < 8; j++) {
                int col = (j < 4) ? (tx * 4 + j) : (64 + tx * 4 + j - 4);
                Ps[rr * 128 + col] = p[j];
            }
            u64v scp = pk2(scf, scf);
            #pragma unroll
            for (int h = 0; h < 8; h++) {
                accM[r][h] = fmul2(accM[r][h], scp);
                accQ[r][h] = fmul2(accQ[r][h], scp);
            }
        }
        __syncthreads();

        // ---- PV: accumulate P*V and P*V^2 over 4 channel chunks ----
        #pragma unroll
        for (int vc = 0; vc < 4; vc++) {
            for (int e = tid; e < 128 * 16; e += 256) {
                int key = e >> 4, c4 = (e & 15) << 2;
                *(float4*)&Vs[key * 64 + c4] =
                    *(const float4*)&g_V[((size_t)b * N_ + k0 + key) * C_ + vc * 64 + c4];
            }
            __syncthreads();
            const u64v* vsb = (const u64v*)Vs;
            #pragma unroll 4
            for (int m = 0; m < 128; m++) {
                float p0f = Ps[ty * 128 + m];
                float p1f = Ps[(ty + 16) * 128 + m];
                u64v p0 = pk2(p0f, p0f), p1 = pk2(p1f, p1f);
                u64v va = vsb[m * 32 + tx * 2], vb = vsb[m * 32 + tx * 2 + 1];
                u64v va2 = fmul2(va, va), vb2 = fmul2(vb, vb);
                accM[0][vc * 2]     = ffma2(p0, va,  accM[0][vc * 2]);
                accM[0][vc * 2 + 1] = ffma2(p0, vb,  accM[0][vc * 2 + 1]);
                accQ[0][vc * 2]     = ffma2(p0, va2, accQ[0][vc * 2]);
                accQ[0][vc * 2 + 1] = ffma2(p0, vb2, accQ[0][vc * 2 + 1]);
                accM[1][vc * 2]     = ffma2(p1, va,  accM[1][vc * 2]);
                accM[1][vc * 2 + 1] = ffma2(p1, vb,  accM[1][vc * 2 + 1]);
                accQ[1][vc * 2]     = ffma2(p1, va2, accQ[1][vc * 2]);
                accQ[1][vc * 2 + 1] = ffma2(p1, vb2, accQ[1][vc * 2 + 1]);
            }
            __syncthreads();
        }
    }

    // ---- finalize: mean/std + mvn epilogue, write [b][c][n] ----
    #pragma unroll
    for (int r = 0; r < 2; r++) {
        float lt = lrow[r];
        #pragma unroll
        for (int off = 8; off; off >>= 1) lt += __shfl_xor_sync(0xffffffffu, lt, off);
        float inv = 1.0f / lt;
        int n = n0 + ((r == 0) ? ty : (ty + 16));
        #pragma unroll
        for (int vc = 0; vc < 4; vc++) {
            #pragma unroll
            for (int h = 0; h < 2; h++) {
                float m0, m1, q0, q1;
                upk2(accM[r][vc * 2 + h], m0, m1);
                upk2(accQ[r][vc * 2 + h], q0, q1);
                int ch0 = vc * 64 + tx * 4 + h * 2;
                #pragma unroll
                for (int e = 0; e < 2; e++) {
                    float mean = ((e == 0) ? m0 : m1) * inv;
                    float m2   = ((e == 0) ? q0 : q1) * inv;
                    float sd = sqrtf(fmaxf(m2 - mean * mean, 0.f));
                    int ch = ch0 + e;
                    size_t oi = ((size_t)(b * C_ + ch)) * N_ + n;
                    float cx = content[oi];
                    out[oi] = sd * (cx - g_cmean[b * C_ + ch]) * g_crstd[b * C_ + ch] + mean;
                }
            }
        }
    }
}

// ---------------- launch ----------------
extern "C" void kernel_launch(void* const* d_in, const int* in_sizes, int n_in,
                              void* d_out, int out_size) {
    const float* content     = (const float*)d_in[0];
    const float* style       = (const float*)d_in[1];
    const float* content_key = (const float*)d_in[2];
    const float* style_key   = (const float*)d_in[3];
    const int*   cmask       = (const int*)d_in[4];
    const int*   smask       = (const int*)d_in[5];
    const float* Wf = (const float*)d_in[6];
    const float* bf = (const float*)d_in[7];
    const float* Wg = (const float*)d_in[8];
    const float* bg = (const float*)d_in[9];
    const float* Wh = (const float*)d_in[10];
    const float* bh = (const float*)d_in[11];
    float* out = (float*)d_out;

    float *Qp, *KTp, *Vp;
    cudaGetSymbolAddress((void**)&Qp,  g_Q);
    cudaGetSymbolAddress((void**)&KTp, g_KT);
    cudaGetSymbolAddress((void**)&Vp,  g_V);
    cudaFuncSetAttribute(attn_kernel, cudaFuncAttributeMaxDynamicSharedMemorySize, SMEM_BYTES);

    stats_kernel<<<B_ * C_, 256>>>(content);
    proj_kernel<CK_, false><<<dim3(N_ / 64, CK_ / 64, B_), 256>>>(content_key, Wf, bf, Qp, CK_);
    proj_kernel<CK_, true ><<<dim3(N_ / 64, CK_ / 64, B_), 256>>>(style_key,   Wg, bg, KTp, CK_);
    proj_kernel<C_,  false><<<dim3(N_ / 64, C_  / 64, B_), 256>>>(style,       Wh, bh, Vp, C_);
    attn_kernel<<<dim3(N_ / 32, B_), 256, SMEM_BYTES>>>(content, cmask, smask, out);
}

// round 5
// speedup vs baseline: 3.7663x; 3.7663x over previous
#include <cuda_runtime.h>
#include <cuda_fp16.h>
#include <cstdint>

#define B_   4
#define C_   256
#define CK_  448
#define N_   4096
#define NEGV (-1e15f)

// ---------------- device scratch ----------------
__device__ __half g_Qh[(size_t)B_*N_*CK_];
__device__ __half g_Ql[(size_t)B_*N_*CK_];
__device__ __half g_Kh[(size_t)B_*N_*CK_];
__device__ __half g_Kl[(size_t)B_*N_*CK_];
__device__ __half g_VTh[(size_t)B_*2*C_*N_];   // [b][j][n], j=2c:v, 2c+1:v^2
__device__ __half g_VTl[(size_t)B_*2*C_*N_];
__device__ float  g_S[(size_t)B_*N_*N_];       // [b][q][k]
__device__ __half g_P[(size_t)B_*N_*N_];       // [b][q][k]
__device__ float  g_l[B_*N_];
__device__ float  g_O[(size_t)B_*N_*2*C_];     // [b][q][j]
__device__ float  g_cmean[B_*C_], g_crstd[B_*C_];

// ---------------- f32x2 helpers (proj GEMM) ----------------
typedef unsigned long long u64v;
__device__ __forceinline__ u64v pk2(float x, float y){u64v r;asm("mov.b64 %0,{%1,%2};":"=l"(r):"f"(x),"f"(y));return r;}
__device__ __forceinline__ void upk2(u64v v,float&x,float&y){asm("mov.b64 {%0,%1},%2;":"=f"(x),"=f"(y):"l"(v));}
__device__ __forceinline__ u64v ffma2(u64v a,u64v b,u64v c){u64v d;asm("fma.rn.f32x2 %0,%1,%2,%3;":"=l"(d):"l"(a),"l"(b),"l"(c));return d;}

// ---------------- mma.sync + cp.async helpers ----------------
__device__ __forceinline__ uint32_t smem_to_u32(const void*p){
    uint32_t a;asm("{ .reg .u64 t; cvta.to.shared.u64 t, %1; cvt.u32.u64 %0, t; }":"=r"(a):"l"(p));return a;}
__device__ __forceinline__ void mma16816(float* c, const uint32_t* a, const uint32_t* b){
    asm volatile("mma.sync.aligned.m16n8k16.row.col.f32.f16.f16.f32 "
        "{%0,%1,%2,%3}, {%4,%5,%6,%7}, {%8,%9}, {%0,%1,%2,%3};"
        : "+f"(c[0]),"+f"(c[1]),"+f"(c[2]),"+f"(c[3])
        : "r"(a[0]),"r"(a[1]),"r"(a[2]),"r"(a[3]), "r"(b[0]),"r"(b[1]));
}
__device__ __forceinline__ void cp16(uint32_t dst, const void* src){
    asm volatile("cp.async.cg.shared.global [%0], [%1], 16;" :: "r"(dst), "l"(src));
}
#define CP_COMMIT() asm volatile("cp.async.commit_group;" ::: "memory")
#define CP_WAIT1()  asm volatile("cp.async.wait_group 1;" ::: "memory")
#define CP_WAIT0()  asm volatile("cp.async.wait_group 0;" ::: "memory")

// ---------------- fast exp on fma pipe ----------------
__device__ __forceinline__ float fast_exp(float x){
    float t = fmaxf(x * 1.4426950408889634f, -126.0f);
    float fi = t + 12582912.0f;
    int i = __float_as_int(fi) - 0x4B400000;
    float f = t - (fi - 12582912.0f);
    float p = 1.5424236e-4f;
    p = fmaf(p,f,1.3333558e-3f); p = fmaf(p,f,9.6181291e-3f);
    p = fmaf(p,f,5.5504109e-2f); p = fmaf(p,f,2.4022651e-1f);
    p = fmaf(p,f,6.9314718e-1f); p = fmaf(p,f,1.0f);
    return __int_as_float(__float_as_int(p) + (i<<23));
}
__device__ __forceinline__ void hsplit(float y, __half& h, __half& l){
    h = __float2half_rn(y); l = __float2half_rn(y - __half2float(h));
}

// ---------------- kernel 1: content stats ----------------
__global__ __launch_bounds__(256) void stats_kernel(const float* __restrict__ content){
    int bc = blockIdx.x, tid = threadIdx.x;
    const float4* x = (const float4*)(content + (size_t)bc*N_);
    float s=0.f,q=0.f;
    for(int i=tid;i<N_/4;i+=256){float4 v=x[i];s+=v.x+v.y+v.z+v.w;q+=v.x*v.x+v.y*v.y+v.z*v.z+v.w*v.w;}
    #pragma unroll
    for(int o=16;o;o>>=1){s+=__shfl_xor_sync(~0u,s,o);q+=__shfl_xor_sync(~0u,q,o);}
    __shared__ float ss[8],qq[8];
    int w=tid>>5,l=tid&31;
    if(l==0){ss[w]=s;qq[w]=q;}
    __syncthreads();
    if(tid==0){
        float S=0,Q=0;
        #pragma unroll
        for(int i=0;i<8;i++){S+=ss[i];Q+=qq[i];}
        float mean=S/(float)N_;
        float var=(Q-(float)N_*mean*mean)/(float)(N_-1);
        g_cmean[bc]=mean; g_crstd[bc]=rsqrtf(var+1e-5f);
    }
}

// ---------------- kernel 2: projection -> fp16 hi/lo ----------------
template<int CIN, int MODE>
__global__ __launch_bounds__(256) void proj_kernel(const float* __restrict__ X,
                                                   const float* __restrict__ W,
                                                   const float* __restrict__ bias,
                                                   __half* __restrict__ Yh,
                                                   __half* __restrict__ Yl){
    __shared__ float Xs[32*64];
    __shared__ float Ws[32*64];
    int b=blockIdx.z, n0=blockIdx.x*64, o0=blockIdx.y*64;
    int tid=threadIdx.x, tx=tid&15, ty=tid>>4;
    u64v acc2[2][4];
    #pragma unroll
    for(int p=0;p<2;p++)
        #pragma unroll
        for(int j=0;j<4;j++) acc2[p][j]=0ull;
    for(int c0=0;c0<CIN;c0+=32){
        __syncthreads();
        for(int e=tid;e<512;e+=256){
            int cc=e>>4, nn=(e&15)<<2;
            *(float4*)&Xs[cc*64+nn]=*(const float4*)&X[((size_t)(b*CIN+c0+cc))*N_+n0+nn];
        }
        for(int e=tid;e<512;e+=256){
            int oo=e>>3, c4=(e&7)<<2;
            float4 v=*(const float4*)&W[(size_t)(o0+oo)*CIN+c0+c4];
            Ws[(c4+0)*64+oo]=v.x; Ws[(c4+1)*64+oo]=v.y; Ws[(c4+2)*64+oo]=v.z; Ws[(c4+3)*64+oo]=v.w;
        }
        __syncthreads();
        #pragma unroll 8
        for(int cc=0;cc<32;cc++){
            u64v x0=*(const u64v*)&Xs[cc*64+ty*4];
            u64v x1=*(const u64v*)&Xs[cc*64+ty*4+2];
            float4 w4=*(const float4*)&Ws[cc*64+tx*4];
            u64v w0=pk2(w4.x,w4.x),w1=pk2(w4.y,w4.y),w2=pk2(w4.z,w4.z),w3=pk2(w4.w,w4.w);
            acc2[0][0]=ffma2(x0,w0,acc2[0][0]); acc2[0][1]=ffma2(x0,w1,acc2[0][1]);
            acc2[0][2]=ffma2(x0,w2,acc2[0][2]); acc2[0][3]=ffma2(x0,w3,acc2[0][3]);
            acc2[1][0]=ffma2(x1,w0,acc2[1][0]); acc2[1][1]=ffma2(x1,w1,acc2[1][1]);
            acc2[1][2]=ffma2(x1,w2,acc2[1][2]); acc2[1][3]=ffma2(x1,w3,acc2[1][3]);
        }
    }
    float a[4][4];
    #pragma unroll
    for(int p=0;p<2;p++)
        #pragma unroll
        for(int j=0;j<4;j++) upk2(acc2[p][j],a[2*p][j],a[2*p+1][j]);
    float4 bo=*(const float4*)&bias[o0+tx*4];
    float bb[4]={bo.x,bo.y,bo.z,bo.w};
    if(MODE==0){
        #pragma unroll
        for(int i=0;i<4;i++){
            __align__(8) __half hh[4], hl[4];
            #pragma unroll
            for(int j=0;j<4;j++){ hsplit(a[i][j]+bb[j], hh[j], hl[j]); }
            size_t base=((size_t)(b*N_)+n0+ty*4+i)*CK_+o0+tx*4;
            *(uint2*)&Yh[base]=*(uint2*)hh; *(uint2*)&Yl[base]=*(uint2*)hl;
        }
    } else {
        #pragma unroll
        for(int j=0;j<4;j++){
            __align__(8) __half vh[4],vl[4],wh[4],wl[4];
            #pragma unroll
            for(int i=0;i<4;i++){
                float y=a[i][j]+bb[j];
                hsplit(y,vh[i],vl[i]);
                hsplit(y*y,wh[i],wl[i]);
            }
            int o=o0+tx*4+j;
            size_t rv=((size_t)b*(2*C_)+2*o)*N_+n0+ty*4;
            *(uint2*)&Yh[rv]=*(uint2*)vh; *(uint2*)&Yh[rv+N_]=*(uint2*)wh;
            *(uint2*)&Yl[rv]=*(uint2*)vl; *(uint2*)&Yl[rv+N_]=*(uint2*)wl;
        }
    }
}

// ---------------- kernel 3: S = Q K^T  (mma.sync m16n8k16, 3-term fp16 split) ----------------
// CTA 128q x 256k, 8 warps (64x64). Stage: padded rows of 40 halfs (80B).
#define SGQ_H 0
#define SGQ_L 10240
#define SGK_H 20480
#define SGK_L 40960
#define SG_STAGE 61440
#define SG_SMEM (2*SG_STAGE)
__global__ __launch_bounds__(256) void sgemm_kernel(){
    extern __shared__ char sm[];
    uint32_t sb = smem_to_u32(sm);
    int tid=threadIdx.x, lane=tid&31, wid=tid>>5;
    int g=lane>>2, tig=lane&3;
    int wq=wid&1, wk=wid>>1;
    int b=blockIdx.z, q0=blockIdx.y*128, k0=blockIdx.x*256;
    const __half* Qh=g_Qh+((size_t)b*N_+q0)*CK_;
    const __half* Ql=g_Ql+((size_t)b*N_+q0)*CK_;
    const __half* Kh=g_Kh+((size_t)b*N_+k0)*CK_;
    const __half* Kl=g_Kl+((size_t)b*N_+k0)*CK_;

    auto issue=[&](int ch, int st){
        uint32_t base = sb + st*SG_STAGE;
        int ck0=ch*32;
        for(int i=tid;i<512;i+=256){
            int r=i>>2, sg=i&3;
            cp16(base+SGQ_H + r*80 + sg*16, Qh + (size_t)r*CK_ + ck0 + sg*8);
            cp16(base+SGQ_L + r*80 + sg*16, Ql + (size_t)r*CK_ + ck0 + sg*8);
        }
        for(int i=tid;i<1024;i+=256){
            int r=i>>2, sg=i&3;
            cp16(base+SGK_H + r*80 + sg*16, Kh + (size_t)r*CK_ + ck0 + sg*8);
            cp16(base+SGK_L + r*80 + sg*16, Kl + (size_t)r*CK_ + ck0 + sg*8);
        }
    };

    float acc[4][8][4];
    #pragma unroll
    for(int mi=0;mi<4;mi++)
        #pragma unroll
        for(int ni=0;ni<8;ni++)
            #pragma unroll
            for(int e=0;e<4;e++) acc[mi][ni][e]=0.f;

    issue(0,0); CP_COMMIT();
    for(int ch=0; ch<14; ch++){
        if(ch+1<14){ issue(ch+1,(ch+1)&1); CP_COMMIT(); CP_WAIT1(); } else { CP_WAIT0(); }
        __syncthreads();
        const char* stg = sm + (ch&1)*SG_STAGE;
        #pragma unroll
        for(int ks=0;ks<2;ks++){
            int kb=ks*16;
            uint32_t bh[8][2], bl[8][2];
            #pragma unroll
            for(int ni=0;ni<8;ni++){
                int kr=wk*64+ni*8+g;
                const char* ph = stg+SGK_H + kr*80 + (kb+tig*2)*2;
                const char* pl = stg+SGK_L + kr*80 + (kb+tig*2)*2;
                bh[ni][0]=*(const uint32_t*)ph;      bh[ni][1]=*(const uint32_t*)(ph+16);
                bl[ni][0]=*(const uint32_t*)pl;      bl[ni][1]=*(const uint32_t*)(pl+16);
            }
            #pragma unroll
            for(int mi=0;mi<4;mi++){
                int qr=wq*64+mi*16+g;
                const char* pa = stg+SGQ_H + qr*80 + (kb+tig*2)*2;
                const char* pb = stg+SGQ_L + qr*80 + (kb+tig*2)*2;
                uint32_t ah[4], al[4];
                ah[0]=*(const uint32_t*)pa;        ah[1]=*(const uint32_t*)(pa+8*80);
                ah[2]=*(const uint32_t*)(pa+16);   ah[3]=*(const uint32_t*)(pa+8*80+16);
                al[0]=*(const uint32_t*)pb;        al[1]=*(const uint32_t*)(pb+8*80);
                al[2]=*(const uint32_t*)(pb+16);   al[3]=*(const uint32_t*)(pb+8*80+16);
                #pragma unroll
                for(int ni=0;ni<8;ni++){
                    mma16816(acc[mi][ni], ah, bh[ni]);
                    mma16816(acc[mi][ni], ah, bl[ni]);
                    mma16816(acc[mi][ni], al, bh[ni]);
                }
            }
        }
        __syncthreads();
    }
    float* So = g_S + ((size_t)b*N_+q0)*N_ + k0;
    #pragma unroll
    for(int mi=0;mi<4;mi++){
        int qr=wq*64+mi*16+g;
        #pragma unroll
        for(int ni=0;ni<8;ni++){
            int kc=wk*64+ni*8+tig*2;
            float2 v0={acc[mi][ni][0],acc[mi][ni][1]};
            float2 v1={acc[mi][ni][2],acc[mi][ni][3]};
            *(float2*)&So[(size_t)qr*N_+kc]     = v0;
            *(float2*)&So[(size_t)(qr+8)*N_+kc] = v1;
        }
    }
}

// ---------------- kernel 4: masked softmax row pass ----------------
__global__ __launch_bounds__(256) void softmax_kernel(const int* __restrict__ cmask,
                                                      const int* __restrict__ smask){
    int b=blockIdx.y, q=blockIdx.x, tid=threadIdx.x;
    const float4* Srow=(const float4*)(g_S+((size_t)b*N_+q)*N_);
    const int4* smr=(const int4*)(smask+b*N_);
    int cm = cmask[b*N_+q]!=0;
    float s[16], mx=-3.4e38f;
    #pragma unroll
    for(int i=0;i<4;i++){
        int k4=tid+i*256;
        float4 v=Srow[k4];
        if(cm){
            int4 m=smr[k4];
            if(m.x==0)v.x=NEGV; if(m.y==0)v.y=NEGV; if(m.z==0)v.z=NEGV; if(m.w==0)v.w=NEGV;
        }
        s[4*i]=v.x;s[4*i+1]=v.y;s[4*i+2]=v.z;s[4*i+3]=v.w;
        mx=fmaxf(mx,fmaxf(fmaxf(v.x,v.y),fmaxf(v.z,v.w)));
    }
    #pragma unroll
    for(int o=16;o;o>>=1) mx=fmaxf(mx,__shfl_xor_sync(~0u,mx,o));
    __shared__ float red[8];
    int w=tid>>5,l=tid&31;
    if(l==0) red[w]=mx;
    __syncthreads();
    float M=red[0];
    #pragma unroll
    for(int i=1;i<8;i++) M=fmaxf(M,red[i]);
    __syncthreads();
    float sum=0.f;
    uint2* Prow=(uint2*)(g_P+((size_t)b*N_+q)*N_);
    #pragma unroll
    for(int i=0;i<4;i++){
        __align__(8) __half h[4];
        #pragma unroll
        for(int j=0;j<4;j++){
            float p=fast_exp(s[4*i+j]-M);
            h[j]=__float2half_rn(p);
            sum+=__half2float(h[j]);
        }
        Prow[tid+i*256]=*(uint2*)h;
    }
    #pragma unroll
    for(int o=16;o;o>>=1) sum+=__shfl_xor_sync(~0u,sum,o);
    if(l==0) red[w]=sum;
    __syncthreads();
    if(tid==0){
        float t=0.f;
        #pragma unroll
        for(int i=0;i<8;i++) t+=red[i];
        g_l[b*N_+q]=t;
    }
}

// ---------------- kernel 5: [mean,m2] = P * VT^T (mma.sync, 2-term) ----------------
// CTA 128q x 256j, 8 warps 64x64, chunk 32 keys, 128 chunks.
#define PVP   0
#define PVV_H 10240
#define PVV_L 30720
#define PV_STAGE 51200
#define PV_SMEM (2*PV_STAGE)
__global__ __launch_bounds__(256) void pv_kernel(){
    extern __shared__ char sm[];
    uint32_t sb = smem_to_u32(sm);
    int tid=threadIdx.x, lane=tid&31, wid=tid>>5;
    int g=lane>>2, tig=lane&3;
    int wq=wid&1, wk=wid>>1;
    int b=blockIdx.z, q0=blockIdx.y*128, j0=blockIdx.x*256;
    const __half* P  = g_P  + ((size_t)b*N_+q0)*N_;
    const __half* Vh = g_VTh+ ((size_t)b*2*C_+j0)*N_;
    const __half* Vl = g_VTl+ ((size_t)b*2*C_+j0)*N_;

    auto issue=[&](int ch, int st){
        uint32_t base = sb + st*PV_STAGE;
        int kk0=ch*32;
        for(int i=tid;i<512;i+=256){
            int r=i>>2, sg=i&3;
            cp16(base+PVP + r*80 + sg*16, P + (size_t)r*N_ + kk0 + sg*8);
        }
        for(int i=tid;i<1024;i+=256){
            int r=i>>2, sg=i&3;
            cp16(base+PVV_H + r*80 + sg*16, Vh + (size_t)r*N_ + kk0 + sg*8);
            cp16(base+PVV_L + r*80 + sg*16, Vl + (size_t)r*N_ + kk0 + sg*8);
        }
    };

    float acc[4][8][4];
    #pragma unroll
    for(int mi=0;mi<4;mi++)
        #pragma unroll
        for(int ni=0;ni<8;ni++)
            #pragma unroll
            for(int e=0;e<4;e++) acc[mi][ni][e]=0.f;

    issue(0,0); CP_COMMIT();
    for(int ch=0; ch<128; ch++){
        if(ch+1<128){ issue(ch+1,(ch+1)&1); CP_COMMIT(); CP_WAIT1(); } else { CP_WAIT0(); }
        __syncthreads();
        const char* stg = sm + (ch&1)*PV_STAGE;
        #pragma unroll
        for(int ks=0;ks<2;ks++){
            int kb=ks*16;
            uint32_t bh[8][2], bl[8][2];
            #pragma unroll
            for(int ni=0;ni<8;ni++){
                int jr=wk*64+ni*8+g;
                const char* ph = stg+PVV_H + jr*80 + (kb+tig*2)*2;
                const char* pl = stg+PVV_L + jr*80 + (kb+tig*2)*2;
                bh[ni][0]=*(const uint32_t*)ph;    bh[ni][1]=*(const uint32_t*)(ph+16);
                bl[ni][0]=*(const uint32_t*)pl;    bl[ni][1]=*(const uint32_t*)(pl+16);
            }
            #pragma unroll
            for(int mi=0;mi<4;mi++){
                int qr=wq*64+mi*16+g;
                const char* pa = stg+PVP + qr*80 + (kb+tig*2)*2;
                uint32_t a[4];
                a[0]=*(const uint32_t*)pa;       a[1]=*(const uint32_t*)(pa+8*80);
                a[2]=*(const uint32_t*)(pa+16);  a[3]=*(const uint32_t*)(pa+8*80+16);
                #pragma unroll
                for(int ni=0;ni<8;ni++){
                    mma16816(acc[mi][ni], a, bh[ni]);
                    mma16816(acc[mi][ni], a, bl[ni]);
                }
            }
        }
        __syncthreads();
    }
    float* Ob = g_O + ((size_t)b*N_+q0)*(2*C_) + j0;
    #pragma unroll
    for(int mi=0;mi<4;mi++){
        int qr=wq*64+mi*16+g;
        #pragma unroll
        for(int ni=0;ni<8;ni++){
            int jc=wk*64+ni*8+tig*2;
            float2 v0={acc[mi][ni][0],acc[mi][ni][1]};
            float2 v1={acc[mi][ni][2],acc[mi][ni][3]};
            *(float2*)&Ob[(size_t)qr*(2*C_)+jc]     = v0;
            *(float2*)&Ob[(size_t)(qr+8)*(2*C_)+jc] = v1;
        }
    }
}

// ---------------- kernel 6: finalize ----------------
__global__ __launch_bounds__(256) void final_kernel(const float* __restrict__ content,
                                                    float* __restrict__ out){
    int b=blockIdx.z, c=blockIdx.y;
    int n=(blockIdx.x*256+threadIdx.x)*4;
    const float* Ob=g_O+(size_t)b*N_*(2*C_);
    float4 l4=*(const float4*)&g_l[b*N_+n];
    float lv[4]={l4.x,l4.y,l4.z,l4.w};
    float cmv=g_cmean[b*C_+c], cr=g_crstd[b*C_+c];
    size_t oi=((size_t)(b*C_+c))*N_+n;
    float4 cx=*(const float4*)&content[oi];
    float ci[4]={cx.x,cx.y,cx.z,cx.w};
    float res[4];
    #pragma unroll
    for(int i=0;i<4;i++){
        float2 mv=*(const float2*)&Ob[(size_t)(n+i)*(2*C_)+2*c];
        float inv=1.0f/lv[i];
        float mean=mv.x*inv, m2=mv.y*inv;
        float sd=sqrtf(fmaxf(m2-mean*mean,0.f));
        res[i]=sd*(ci[i]-cmv)*cr+mean;
    }
    float4 ro={res[0],res[1],res[2],res[3]};
    *(float4*)&out[oi]=ro;
}

// ---------------- launch ----------------
extern "C" void kernel_launch(void* const* d_in, const int* in_sizes, int n_in,
                              void* d_out, int out_size){
    const float* content     = (const float*)d_in[0];
    const float* style       = (const float*)d_in[1];
    const float* content_key = (const float*)d_in[2];
    const float* style_key   = (const float*)d_in[3];
    const int*   cmask       = (const int*)d_in[4];
    const int*   smask       = (const int*)d_in[5];
    const float* Wf=(const float*)d_in[6];  const float* bf=(const float*)d_in[7];
    const float* Wg=(const float*)d_in[8];  const float* bg=(const float*)d_in[9];
    const float* Wh=(const float*)d_in[10]; const float* bh=(const float*)d_in[11];
    float* out=(float*)d_out;

    __half *qh,*ql,*kh,*kl,*vth,*vtl;
    cudaGetSymbolAddress((void**)&qh,  g_Qh);
    cudaGetSymbolAddress((void**)&ql,  g_Ql);
    cudaGetSymbolAddress((void**)&kh,  g_Kh);
    cudaGetSymbolAddress((void**)&kl,  g_Kl);
    cudaGetSymbolAddress((void**)&vth, g_VTh);
    cudaGetSymbolAddress((void**)&vtl, g_VTl);
    cudaFuncSetAttribute(sgemm_kernel, cudaFuncAttributeMaxDynamicSharedMemorySize, SG_SMEM);
    cudaFuncSetAttribute(pv_kernel,    cudaFuncAttributeMaxDynamicSharedMemorySize, PV_SMEM);

    stats_kernel<<<B_*C_, 256>>>(content);
    proj_kernel<CK_,0><<<dim3(64, 7, B_), 256>>>(content_key, Wf, bf, qh, ql);
    proj_kernel<CK_,0><<<dim3(64, 7, B_), 256>>>(style_key,   Wg, bg, kh, kl);
    proj_kernel<C_, 1><<<dim3(64, 4, B_), 256>>>(style,       Wh, bh, vth, vtl);
    sgemm_kernel<<<dim3(16, 32, B_), 256, SG_SMEM>>>();
    softmax_kernel<<<dim3(N_, B_), 256>>>(cmask, smask);
    pv_kernel<<<dim3(2, 32, B_), 256, PV_SMEM>>>();
    final_kernel<<<dim3(4, C_, B_), 256>>>(content, out);
}

// round 6
// speedup vs baseline: 4.8224x; 1.2804x over previous
#include <cuda_runtime.h>
#include <cuda_fp16.h>
#include <cstdint>

#define B_   4
#define C_   256
#define CK_  448
#define N_   4096
#define NEGV (-1e15f)

// ---------------- device scratch ----------------
__device__ __half g_Qh[(size_t)B_*N_*CK_];
__device__ __half g_Kh[(size_t)B_*N_*CK_];
__device__ __half g_Kl[(size_t)B_*N_*CK_];
__device__ __half g_VTh[(size_t)B_*2*C_*N_];   // [b][j][n], j=2c:v, 2c+1:v^2
__device__ float  g_S[(size_t)B_*N_*N_];       // [b][q][k]
__device__ __half g_P[(size_t)B_*N_*N_];       // [b][q][k]
__device__ float  g_l[B_*N_];
__device__ float  g_O[(size_t)B_*N_*2*C_];     // [b][q][j]
__device__ float  g_cmean[B_*C_], g_crstd[B_*C_];

// ---------------- f32x2 helpers (proj GEMM) ----------------
typedef unsigned long long u64v;
__device__ __forceinline__ u64v pk2(float x, float y){u64v r;asm("mov.b64 %0,{%1,%2};":"=l"(r):"f"(x),"f"(y));return r;}
__device__ __forceinline__ void upk2(u64v v,float&x,float&y){asm("mov.b64 {%0,%1},%2;":"=f"(x),"=f"(y):"l"(v));}
__device__ __forceinline__ u64v ffma2(u64v a,u64v b,u64v c){u64v d;asm("fma.rn.f32x2 %0,%1,%2,%3;":"=l"(d):"l"(a),"l"(b),"l"(c));return d;}

// ---------------- mma.sync / ldmatrix / cp.async ----------------
__device__ __forceinline__ uint32_t smem_to_u32(const void*p){
    uint32_t a;asm("{ .reg .u64 t; cvta.to.shared.u64 t, %1; cvt.u32.u64 %0, t; }":"=r"(a):"l"(p));return a;}
__device__ __forceinline__ void mma16816(float* c, const uint32_t* a, const uint32_t* b){
    asm volatile("mma.sync.aligned.m16n8k16.row.col.f32.f16.f16.f32 "
        "{%0,%1,%2,%3}, {%4,%5,%6,%7}, {%8,%9}, {%0,%1,%2,%3};"
        : "+f"(c[0]),"+f"(c[1]),"+f"(c[2]),"+f"(c[3])
        : "r"(a[0]),"r"(a[1]),"r"(a[2]),"r"(a[3]), "r"(b[0]),"r"(b[1]));
}
__device__ __forceinline__ void ldm4(uint32_t* r, uint32_t addr){
    asm volatile("ldmatrix.sync.aligned.m8n8.x4.shared.b16 {%0,%1,%2,%3}, [%4];"
        :"=r"(r[0]),"=r"(r[1]),"=r"(r[2]),"=r"(r[3]):"r"(addr));
}
__device__ __forceinline__ void cp16(uint32_t dst, const void* src){
    asm volatile("cp.async.cg.shared.global [%0], [%1], 16;" :: "r"(dst), "l"(src));
}
#define CP_COMMIT() asm volatile("cp.async.commit_group;" ::: "memory")
#define CP_WAIT2()  asm volatile("cp.async.wait_group 2;" ::: "memory")
#define CP_WAIT1()  asm volatile("cp.async.wait_group 1;" ::: "memory")
#define CP_WAIT0()  asm volatile("cp.async.wait_group 0;" ::: "memory")

// ---------------- fast exp on fma pipe ----------------
__device__ __forceinline__ float fast_exp(float x){
    float t = fmaxf(x * 1.4426950408889634f, -126.0f);
    float fi = t + 12582912.0f;
    int i = __float_as_int(fi) - 0x4B400000;
    float f = t - (fi - 12582912.0f);
    float p = 1.5424236e-4f;
    p = fmaf(p,f,1.3333558e-3f); p = fmaf(p,f,9.6181291e-3f);
    p = fmaf(p,f,5.5504109e-2f); p = fmaf(p,f,2.4022651e-1f);
    p = fmaf(p,f,6.9314718e-1f); p = fmaf(p,f,1.0f);
    return __int_as_float(__float_as_int(p) + (i<<23));
}
__device__ __forceinline__ void hsplit(float y, __half& h, __half& l){
    h = __float2half_rn(y); l = __float2half_rn(y - __half2float(h));
}

// ---------------- kernel 1: content stats ----------------
__global__ __launch_bounds__(256) void stats_kernel(const float* __restrict__ content){
    int bc = blockIdx.x, tid = threadIdx.x;
    const float4* x = (const float4*)(content + (size_t)bc*N_);
    float s=0.f,q=0.f;
    for(int i=tid;i<N_/4;i+=256){float4 v=x[i];s+=v.x+v.y+v.z+v.w;q+=v.x*v.x+v.y*v.y+v.z*v.z+v.w*v.w;}
    #pragma unroll
    for(int o=16;o;o>>=1){s+=__shfl_xor_sync(~0u,s,o);q+=__shfl_xor_sync(~0u,q,o);}
    __shared__ float ss[8],qq[8];
    int w=tid>>5,l=tid&31;
    if(l==0){ss[w]=s;qq[w]=q;}
    __syncthreads();
    if(tid==0){
        float S=0,Q=0;
        #pragma unroll
        for(int i=0;i<8;i++){S+=ss[i];Q+=qq[i];}
        float mean=S/(float)N_;
        float var=(Q-(float)N_*mean*mean)/(float)(N_-1);
        g_cmean[bc]=mean; g_crstd[bc]=rsqrtf(var+1e-5f);
    }
}

// ---------------- kernel 2: projection ----------------
// MODE 0: Yh[b][n][CK_] (h only, Q). MODE 2: Yh+Yl (K). MODE 1: VT h-only (v, v^2).
template<int CIN, int MODE>
__global__ __launch_bounds__(256) void proj_kernel(const float* __restrict__ X,
                                                   const float* __restrict__ W,
                                                   const float* __restrict__ bias,
                                                   __half* __restrict__ Yh,
                                                   __half* __restrict__ Yl){
    __shared__ float Xs[32*64];
    __shared__ float Ws[32*64];
    int b=blockIdx.z, n0=blockIdx.x*64, o0=blockIdx.y*64;
    int tid=threadIdx.x, tx=tid&15, ty=tid>>4;
    u64v acc2[2][4];
    #pragma unroll
    for(int p=0;p<2;p++)
        #pragma unroll
        for(int j=0;j<4;j++) acc2[p][j]=0ull;
    for(int c0=0;c0<CIN;c0+=32){
        __syncthreads();
        for(int e=tid;e<512;e+=256){
            int cc=e>>4, nn=(e&15)<<2;
            *(float4*)&Xs[cc*64+nn]=*(const float4*)&X[((size_t)(b*CIN+c0+cc))*N_+n0+nn];
        }
        for(int e=tid;e<512;e+=256){
            int oo=e>>3, c4=(e&7)<<2;
            float4 v=*(const float4*)&W[(size_t)(o0+oo)*CIN+c0+c4];
            Ws[(c4+0)*64+oo]=v.x; Ws[(c4+1)*64+oo]=v.y; Ws[(c4+2)*64+oo]=v.z; Ws[(c4+3)*64+oo]=v.w;
        }
        __syncthreads();
        #pragma unroll 8
        for(int cc=0;cc<32;cc++){
            u64v x0=*(const u64v*)&Xs[cc*64+ty*4];
            u64v x1=*(const u64v*)&Xs[cc*64+ty*4+2];
            float4 w4=*(const float4*)&Ws[cc*64+tx*4];
            u64v w0=pk2(w4.x,w4.x),w1=pk2(w4.y,w4.y),w2=pk2(w4.z,w4.z),w3=pk2(w4.w,w4.w);
            acc2[0][0]=ffma2(x0,w0,acc2[0][0]); acc2[0][1]=ffma2(x0,w1,acc2[0][1]);
            acc2[0][2]=ffma2(x0,w2,acc2[0][2]); acc2[0][3]=ffma2(x0,w3,acc2[0][3]);
            acc2[1][0]=ffma2(x1,w0,acc2[1][0]); acc2[1][1]=ffma2(x1,w1,acc2[1][1]);
            acc2[1][2]=ffma2(x1,w2,acc2[1][2]); acc2[1][3]=ffma2(x1,w3,acc2[1][3]);
        }
    }
    float a[4][4];
    #pragma unroll
    for(int p=0;p<2;p++)
        #pragma unroll
        for(int j=0;j<4;j++) upk2(acc2[p][j],a[2*p][j],a[2*p+1][j]);
    float4 bo=*(const float4*)&bias[o0+tx*4];
    float bb[4]={bo.x,bo.y,bo.z,bo.w};
    if(MODE==0){
        #pragma unroll
        for(int i=0;i<4;i++){
            __align__(8) __half hh[4];
            #pragma unroll
            for(int j=0;j<4;j++) hh[j]=__float2half_rn(a[i][j]+bb[j]);
            size_t base=((size_t)(b*N_)+n0+ty*4+i)*CK_+o0+tx*4;
            *(uint2*)&Yh[base]=*(uint2*)hh;
        }
    } else if(MODE==2){
        #pragma unroll
        for(int i=0;i<4;i++){
            __align__(8) __half hh[4], hl[4];
            #pragma unroll
            for(int j=0;j<4;j++){ hsplit(a[i][j]+bb[j], hh[j], hl[j]); }
            size_t base=((size_t)(b*N_)+n0+ty*4+i)*CK_+o0+tx*4;
            *(uint2*)&Yh[base]=*(uint2*)hh; *(uint2*)&Yl[base]=*(uint2*)hl;
        }
    } else {
        #pragma unroll
        for(int j=0;j<4;j++){
            __align__(8) __half vh[4], wh[4];
            #pragma unroll
            for(int i=0;i<4;i++){
                float y=a[i][j]+bb[j];
                vh[i]=__float2half_rn(y);
                wh[i]=__float2half_rn(y*y);
            }
            int o=o0+tx*4+j;
            size_t rv=((size_t)b*(2*C_)+2*o)*N_+n0+ty*4;
            *(uint2*)&Yh[rv]=*(uint2*)vh; *(uint2*)&Yh[rv+N_]=*(uint2*)wh;
        }
    }
}

// ---------------- kernel 3: S = Q K^T  (mma.sync + ldmatrix, 2-term) ----------------
// CTA 128q x 256k, 8 warps (64x64). Chunk = 64 halves of CK (7 chunks), 2 stages.
// Stage rows padded to 144B.
#define SG_Q  0
#define SG_KH 18432
#define SG_KL 55296
#define SG_STAGE 92160
#define SG_SMEM (2*SG_STAGE)
__global__ __launch_bounds__(256) void sgemm_kernel(){
    extern __shared__ char sm[];
    uint32_t sb = smem_to_u32(sm);
    int tid=threadIdx.x, lane=tid&31, wid=tid>>5;
    int g=lane>>2, tig=lane&3;
    int wq=wid&1, wk=wid>>1;
    int lrow=lane&15, lcol=lane>>4;
    int b=blockIdx.z, q0=blockIdx.y*128, k0=blockIdx.x*256;
    const __half* Qg=g_Qh+((size_t)b*N_+q0)*CK_;
    const __half* Khg=g_Kh+((size_t)b*N_+k0)*CK_;
    const __half* Klg=g_Kl+((size_t)b*N_+k0)*CK_;

    auto issue=[&](int ch, int st){
        uint32_t base = sb + st*SG_STAGE;
        int ck0=ch*64;
        for(int i=tid;i<1024;i+=256){
            int r=i>>3, s=i&7;
            cp16(base+SG_Q + r*144 + s*16, Qg + (size_t)r*CK_ + ck0 + s*8);
        }
        for(int i=tid;i<2048;i+=256){
            int r=i>>3, s=i&7;
            cp16(base+SG_KH + r*144 + s*16, Khg + (size_t)r*CK_ + ck0 + s*8);
            cp16(base+SG_KL + r*144 + s*16, Klg + (size_t)r*CK_ + ck0 + s*8);
        }
    };

    float acc[4][8][4];
    #pragma unroll
    for(int mi=0;mi<4;mi++)
        #pragma unroll
        for(int ni=0;ni<8;ni++)
            #pragma unroll
            for(int e=0;e<4;e++) acc[mi][ni][e]=0.f;

    issue(0,0); CP_COMMIT();
    for(int ch=0; ch<7; ch++){
        if(ch+1<7){ issue(ch+1,(ch+1)&1); CP_COMMIT(); CP_WAIT1(); } else { CP_WAIT0(); }
        __syncthreads();
        uint32_t stg = sb + (ch&1)*SG_STAGE;
        #pragma unroll
        for(int ks=0;ks<4;ks++){
            int kbo = (ks*16 + lcol*8)*2;   // byte offset in row
            uint32_t bh[8][2], bl[8][2];
            #pragma unroll
            for(int nb=0;nb<4;nb++){
                uint32_t r4[4];
                uint32_t addr = stg+SG_KH + (wk*64+nb*16+lrow)*144 + kbo;
                ldm4(r4, addr);
                bh[2*nb][0]=r4[0]; bh[2*nb+1][0]=r4[1]; bh[2*nb][1]=r4[2]; bh[2*nb+1][1]=r4[3];
                addr = stg+SG_KL + (wk*64+nb*16+lrow)*144 + kbo;
                ldm4(r4, addr);
                bl[2*nb][0]=r4[0]; bl[2*nb+1][0]=r4[1]; bl[2*nb][1]=r4[2]; bl[2*nb+1][1]=r4[3];
            }
            #pragma unroll
            for(int mi=0;mi<4;mi++){
                uint32_t a[4];
                ldm4(a, stg+SG_Q + (wq*64+mi*16+lrow)*144 + kbo);
                #pragma unroll
                for(int ni=0;ni<8;ni++){
                    mma16816(acc[mi][ni], a, bh[ni]);
                    mma16816(acc[mi][ni], a, bl[ni]);
                }
            }
        }
        __syncthreads();
    }
    float* So = g_S + ((size_t)b*N_+q0)*N_ + k0;
    #pragma unroll
    for(int mi=0;mi<4;mi++){
        int qr=wq*64+mi*16+g;
        #pragma unroll
        for(int ni=0;ni<8;ni++){
            int kc=wk*64+ni*8+tig*2;
            float2 v0={acc[mi][ni][0],acc[mi][ni][1]};
            float2 v1={acc[mi][ni][2],acc[mi][ni][3]};
            *(float2*)&So[(size_t)qr*N_+kc]     = v0;
            *(float2*)&So[(size_t)(qr+8)*N_+kc] = v1;
        }
    }
}

// ---------------- kernel 4: masked softmax row pass ----------------
__global__ __launch_bounds__(256) void softmax_kernel(const int* __restrict__ cmask,
                                                      const int* __restrict__ smask){
    int b=blockIdx.y, q=blockIdx.x, tid=threadIdx.x;
    const float4* Srow=(const float4*)(g_S+((size_t)b*N_+q)*N_);
    const int4* smr=(const int4*)(smask+b*N_);
    int cm = cmask[b*N_+q]!=0;
    float s[16], mx=-3.4e38f;
    #pragma unroll
    for(int i=0;i<4;i++){
        int k4=tid+i*256;
        float4 v=Srow[k4];
        if(cm){
            int4 m=smr[k4];
            if(m.x==0)v.x=NEGV; if(m.y==0)v.y=NEGV; if(m.z==0)v.z=NEGV; if(m.w==0)v.w=NEGV;
        }
        s[4*i]=v.x;s[4*i+1]=v.y;s[4*i+2]=v.z;s[4*i+3]=v.w;
        mx=fmaxf(mx,fmaxf(fmaxf(v.x,v.y),fmaxf(v.z,v.w)));
    }
    #pragma unroll
    for(int o=16;o;o>>=1) mx=fmaxf(mx,__shfl_xor_sync(~0u,mx,o));
    __shared__ float red[8];
    int w=tid>>5,l=tid&31;
    if(l==0) red[w]=mx;
    __syncthreads();
    float M=red[0];
    #pragma unroll
    for(int i=1;i<8;i++) M=fmaxf(M,red[i]);
    __syncthreads();
    float sum=0.f;
    uint2* Prow=(uint2*)(g_P+((size_t)b*N_+q)*N_);
    #pragma unroll
    for(int i=0;i<4;i++){
        __align__(8) __half h[4];
        #pragma unroll
        for(int j=0;j<4;j++){
            float p=fast_exp(s[4*i+j]-M);
            h[j]=__float2half_rn(p);
            sum+=__half2float(h[j]);
        }
        Prow[tid+i*256]=*(uint2*)h;
    }
    #pragma unroll
    for(int o=16;o;o>>=1) sum+=__shfl_xor_sync(~0u,sum,o);
    if(l==0) red[w]=sum;
    __syncthreads();
    if(tid==0){
        float t=0.f;
        #pragma unroll
        for(int i=0;i<8;i++) t+=red[i];
        g_l[b*N_+q]=t;
    }
}

// ---------------- kernel 5: [mean,m2] = P * VT^T (mma.sync + ldmatrix, 1-term) ----------------
// CTA 128q x 256j, 8 warps 64x64. Chunk 64 keys (64 chunks), 3 stages.
#define PV_P 0
#define PV_V 18432
#define PV_STAGE 55296
#define PV_SMEM (3*PV_STAGE)
__global__ __launch_bounds__(256) void pv_kernel(){
    extern __shared__ char sm[];
    uint32_t sb = smem_to_u32(sm);
    int tid=threadIdx.x, lane=tid&31, wid=tid>>5;
    int g=lane>>2, tig=lane&3;
    int wq=wid&1, wk=wid>>1;
    int lrow=lane&15, lcol=lane>>4;
    int b=blockIdx.z, q0=blockIdx.y*128, j0=blockIdx.x*256;
    const __half* Pg = g_P  + ((size_t)b*N_+q0)*N_;
    const __half* Vg = g_VTh+ ((size_t)b*2*C_+j0)*N_;

    auto issue=[&](int ch, int st){
        uint32_t base = sb + st*PV_STAGE;
        int kk0=ch*64;
        for(int i=tid;i<1024;i+=256){
            int r=i>>3, s=i&7;
            cp16(base+PV_P + r*144 + s*16, Pg + (size_t)r*N_ + kk0 + s*8);
        }
        for(int i=tid;i<2048;i+=256){
            int r=i>>3, s=i&7;
            cp16(base+PV_V + r*144 + s*16, Vg + (size_t)r*N_ + kk0 + s*8);
        }
    };

    float acc[4][8][4];
    #pragma unroll
    for(int mi=0;mi<4;mi++)
        #pragma unroll
        for(int ni=0;ni<8;ni++)
            #pragma unroll
            for(int e=0;e<4;e++) acc[mi][ni][e]=0.f;

    issue(0,0); CP_COMMIT();
    issue(1,1); CP_COMMIT();
    int st=2;
    for(int ch=0; ch<64; ch++){
        if(ch+2<64){ issue(ch+2,st); CP_COMMIT(); st=(st+1==3)?0:st+1; CP_WAIT2(); }
        else if(ch+1<64){ CP_WAIT1(); }
        else { CP_WAIT0(); }
        __syncthreads();
        uint32_t stg = sb + (ch%3)*PV_STAGE;
        #pragma unroll
        for(int ks=0;ks<4;ks++){
            int kbo = (ks*16 + lcol*8)*2;
            uint32_t bh[8][2];
            #pragma unroll
            for(int nb=0;nb<4;nb++){
                uint32_t r4[4];
                ldm4(r4, stg+PV_V + (wk*64+nb*16+lrow)*144 + kbo);
                bh[2*nb][0]=r4[0]; bh[2*nb+1][0]=r4[1]; bh[2*nb][1]=r4[2]; bh[2*nb+1][1]=r4[3];
            }
            #pragma unroll
            for(int mi=0;mi<4;mi++){
                uint32_t a[4];
                ldm4(a, stg+PV_P + (wq*64+mi*16+lrow)*144 + kbo);
                #pragma unroll
                for(int ni=0;ni<8;ni++) mma16816(acc[mi][ni], a, bh[ni]);
            }
        }
        __syncthreads();
    }
    float* Ob = g_O + ((size_t)b*N_+q0)*(2*C_) + j0;
    #pragma unroll
    for(int mi=0;mi<4;mi++){
        int qr=wq*64+mi*16+g;
        #pragma unroll
        for(int ni=0;ni<8;ni++){
            int jc=wk*64+ni*8+tig*2;
            float2 v0={acc[mi][ni][0],acc[mi][ni][1]};
            float2 v1={acc[mi][ni][2],acc[mi][ni][3]};
            *(float2*)&Ob[(size_t)qr*(2*C_)+jc]     = v0;
            *(float2*)&Ob[(size_t)(qr+8)*(2*C_)+jc] = v1;
        }
    }
}

// ---------------- kernel 6: finalize ----------------
__global__ __launch_bounds__(256) void final_kernel(const float* __restrict__ content,
                                                    float* __restrict__ out){
    int b=blockIdx.z, c=blockIdx.y;
    int n=(blockIdx.x*256+threadIdx.x)*4;
    const float* Ob=g_O+(size_t)b*N_*(2*C_);
    float4 l4=*(const float4*)&g_l[b*N_+n];
    float lv[4]={l4.x,l4.y,l4.z,l4.w};
    float cmv=g_cmean[b*C_+c], cr=g_crstd[b*C_+c];
    size_t oi=((size_t)(b*C_+c))*N_+n;
    float4 cx=*(const float4*)&content[oi];
    float ci[4]={cx.x,cx.y,cx.z,cx.w};
    float res[4];
    #pragma unroll
    for(int i=0;i<4;i++){
        float2 mv=*(const float2*)&Ob[(size_t)(n+i)*(2*C_)+2*c];
        float inv=1.0f/lv[i];
        float mean=mv.x*inv, m2=mv.y*inv;
        float sd=sqrtf(fmaxf(m2-mean*mean,0.f));
        res[i]=sd*(ci[i]-cmv)*cr+mean;
    }
    float4 ro={res[0],res[1],res[2],res[3]};
    *(float4*)&out[oi]=ro;
}

// ---------------- launch ----------------
extern "C" void kernel_launch(void* const* d_in, const int* in_sizes, int n_in,
                              void* d_out, int out_size){
    const float* content     = (const float*)d_in[0];
    const float* style       = (const float*)d_in[1];
    const float* content_key = (const float*)d_in[2];
    const float* style_key   = (const float*)d_in[3];
    const int*   cmask       = (const int*)d_in[4];
    const int*   smask       = (const int*)d_in[5];
    const float* Wf=(const float*)d_in[6];  const float* bf=(const float*)d_in[7];
    const float* Wg=(const float*)d_in[8];  const float* bg=(const float*)d_in[9];
    const float* Wh=(const float*)d_in[10]; const float* bh=(const float*)d_in[11];
    float* out=(float*)d_out;

    __half *qh,*kh,*kl,*vth;
    cudaGetSymbolAddress((void**)&qh,  g_Qh);
    cudaGetSymbolAddress((void**)&kh,  g_Kh);
    cudaGetSymbolAddress((void**)&kl,  g_Kl);
    cudaGetSymbolAddress((void**)&vth, g_VTh);
    cudaFuncSetAttribute(sgemm_kernel, cudaFuncAttributeMaxDynamicSharedMemorySize, SG_SMEM);
    cudaFuncSetAttribute(pv_kernel,    cudaFuncAttributeMaxDynamicSharedMemorySize, PV_SMEM);

    stats_kernel<<<B_*C_, 256>>>(content);
    proj_kernel<CK_,0><<<dim3(64, 7, B_), 256>>>(content_key, Wf, bf, qh, (__half*)0);
    proj_kernel<CK_,2><<<dim3(64, 7, B_), 256>>>(style_key,   Wg, bg, kh, kl);
    proj_kernel<C_, 1><<<dim3(64, 4, B_), 256>>>(style,       Wh, bh, vth, (__half*)0);
    sgemm_kernel<<<dim3(16, 32, B_), 256, SG_SMEM>>>();
    softmax_kernel<<<dim3(N_, B_), 256>>>(cmask, smask);
    pv_kernel<<<dim3(2, 32, B_), 256, PV_SMEM>>>();
    final_kernel<<<dim3(4, C_, B_), 256>>>(content, out);
}

// round 7
// speedup vs baseline: 6.2262x; 1.2911x over previous
#include <cuda_runtime.h>
#include <cuda_fp16.h>
#include <cstdint>

#define B_   4
#define C_   256
#define CK_  448
#define N_   4096
#define NEGV (-1e15f)

// ---------------- device scratch ----------------
__device__ __half g_Qh[(size_t)B_*N_*CK_];
__device__ __half g_Kh[(size_t)B_*N_*CK_];
__device__ __half g_VTh[(size_t)B_*2*C_*N_];   // [b][j][n], j=2c:v, 2c+1:v^2
__device__ float  g_S[(size_t)B_*N_*N_];       // [b][q][k]
__device__ __half g_P[(size_t)B_*N_*N_];       // [b][q][k]
__device__ float  g_l[B_*N_];
__device__ float  g_O[(size_t)B_*N_*2*C_];     // [b][q][j]
__device__ float  g_cmean[B_*C_], g_crstd[B_*C_];

// ---------------- f32x2 helpers (proj GEMM) ----------------
typedef unsigned long long u64v;
__device__ __forceinline__ u64v pk2(float x, float y){u64v r;asm("mov.b64 %0,{%1,%2};":"=l"(r):"f"(x),"f"(y));return r;}
__device__ __forceinline__ void upk2(u64v v,float&x,float&y){asm("mov.b64 {%0,%1},%2;":"=f"(x),"=f"(y):"l"(v));}
__device__ __forceinline__ u64v ffma2(u64v a,u64v b,u64v c){u64v d;asm("fma.rn.f32x2 %0,%1,%2,%3;":"=l"(d):"l"(a),"l"(b),"l"(c));return d;}

// ---------------- mma.sync / ldmatrix / cp.async ----------------
__device__ __forceinline__ uint32_t smem_to_u32(const void*p){
    uint32_t a;asm("{ .reg .u64 t; cvta.to.shared.u64 t, %1; cvt.u32.u64 %0, t; }":"=r"(a):"l"(p));return a;}
__device__ __forceinline__ void mma16816(float* c, const uint32_t* a, const uint32_t* b){
    asm volatile("mma.sync.aligned.m16n8k16.row.col.f32.f16.f16.f32 "
        "{%0,%1,%2,%3}, {%4,%5,%6,%7}, {%8,%9}, {%0,%1,%2,%3};"
        : "+f"(c[0]),"+f"(c[1]),"+f"(c[2]),"+f"(c[3])
        : "r"(a[0]),"r"(a[1]),"r"(a[2]),"r"(a[3]), "r"(b[0]),"r"(b[1]));
}
__device__ __forceinline__ void ldm4(uint32_t* r, uint32_t addr){
    asm volatile("ldmatrix.sync.aligned.m8n8.x4.shared.b16 {%0,%1,%2,%3}, [%4];"
        :"=r"(r[0]),"=r"(r[1]),"=r"(r[2]),"=r"(r[3]):"r"(addr));
}
__device__ __forceinline__ void cp16(uint32_t dst, const void* src){
    asm volatile("cp.async.cg.shared.global [%0], [%1], 16;" :: "r"(dst), "l"(src));
}
#define CP_COMMIT() asm volatile("cp.async.commit_group;" ::: "memory")
#define CP_WAIT2()  asm volatile("cp.async.wait_group 2;" ::: "memory")
#define CP_WAIT1()  asm volatile("cp.async.wait_group 1;" ::: "memory")
#define CP_WAIT0()  asm volatile("cp.async.wait_group 0;" ::: "memory")

// ---------------- fast exp on fma pipe ----------------
__device__ __forceinline__ float fast_exp(float x){
    float t = fmaxf(x * 1.4426950408889634f, -126.0f);
    float fi = t + 12582912.0f;
    int i = __float_as_int(fi) - 0x4B400000;
    float f = t - (fi - 12582912.0f);
    float p = 1.5424236e-4f;
    p = fmaf(p,f,1.3333558e-3f); p = fmaf(p,f,9.6181291e-3f);
    p = fmaf(p,f,5.5504109e-2f); p = fmaf(p,f,2.4022651e-1f);
    p = fmaf(p,f,6.9314718e-1f); p = fmaf(p,f,1.0f);
    return __int_as_float(__float_as_int(p) + (i<<23));
}

// ---------------- kernel 1: content stats ----------------
__global__ __launch_bounds__(256) void stats_kernel(const float* __restrict__ content){
    int bc = blockIdx.x, tid = threadIdx.x;
    const float4* x = (const float4*)(content + (size_t)bc*N_);
    float s=0.f,q=0.f;
    for(int i=tid;i<N_/4;i+=256){float4 v=x[i];s+=v.x+v.y+v.z+v.w;q+=v.x*v.x+v.y*v.y+v.z*v.z+v.w*v.w;}
    #pragma unroll
    for(int o=16;o;o>>=1){s+=__shfl_xor_sync(~0u,s,o);q+=__shfl_xor_sync(~0u,q,o);}
    __shared__ float ss[8],qq[8];
    int w=tid>>5,l=tid&31;
    if(l==0){ss[w]=s;qq[w]=q;}
    __syncthreads();
    if(tid==0){
        float S=0,Q=0;
        #pragma unroll
        for(int i=0;i<8;i++){S+=ss[i];Q+=qq[i];}
        float mean=S/(float)N_;
        float var=(Q-(float)N_*mean*mean)/(float)(N_-1);
        g_cmean[bc]=mean; g_crstd[bc]=rsqrtf(var+1e-5f);
    }
}

// ---------------- kernel 2: projection (widened SIMT) ----------------
// CTA 128n x 64o; thread 8n x 4o.
// MODE 0: Yh[b][n][CK_] fp16. MODE 1: VT[b][2o(+1)][n] with v and v^2.
template<int CIN, int MODE>
__global__ __launch_bounds__(256) void proj_kernel(const float* __restrict__ X,
                                                   const float* __restrict__ W,
                                                   const float* __restrict__ bias,
                                                   __half* __restrict__ Yh){
    __shared__ float Xs[32*128];
    __shared__ float Ws[32*64];
    int b=blockIdx.z, n0=blockIdx.x*128, o0=blockIdx.y*64;
    int tid=threadIdx.x, tx=tid&15, ty=tid>>4;
    u64v acc2[4][4];
    #pragma unroll
    for(int p=0;p<4;p++)
        #pragma unroll
        for(int j=0;j<4;j++) acc2[p][j]=0ull;
    for(int c0=0;c0<CIN;c0+=32){
        __syncthreads();
        for(int e=tid;e<1024;e+=256){
            int cc=e>>5, nn=(e&31)<<2;
            *(float4*)&Xs[cc*128+nn]=*(const float4*)&X[((size_t)(b*CIN+c0+cc))*N_+n0+nn];
        }
        for(int e=tid;e<512;e+=256){
            int oo=e>>3, c4=(e&7)<<2;
            float4 v=*(const float4*)&W[(size_t)(o0+oo)*CIN+c0+c4];
            Ws[(c4+0)*64+oo]=v.x; Ws[(c4+1)*64+oo]=v.y; Ws[(c4+2)*64+oo]=v.z; Ws[(c4+3)*64+oo]=v.w;
        }
        __syncthreads();
        #pragma unroll 4
        for(int cc=0;cc<32;cc++){
            const u64v* xr=(const u64v*)&Xs[cc*128+ty*8];
            u64v x0=xr[0], x1=xr[1], x2=xr[2], x3=xr[3];
            float4 w4=*(const float4*)&Ws[cc*64+tx*4];
            u64v w0=pk2(w4.x,w4.x),w1=pk2(w4.y,w4.y),w2=pk2(w4.z,w4.z),w3=pk2(w4.w,w4.w);
            acc2[0][0]=ffma2(x0,w0,acc2[0][0]); acc2[0][1]=ffma2(x0,w1,acc2[0][1]);
            acc2[0][2]=ffma2(x0,w2,acc2[0][2]); acc2[0][3]=ffma2(x0,w3,acc2[0][3]);
            acc2[1][0]=ffma2(x1,w0,acc2[1][0]); acc2[1][1]=ffma2(x1,w1,acc2[1][1]);
            acc2[1][2]=ffma2(x1,w2,acc2[1][2]); acc2[1][3]=ffma2(x1,w3,acc2[1][3]);
            acc2[2][0]=ffma2(x2,w0,acc2[2][0]); acc2[2][1]=ffma2(x2,w1,acc2[2][1]);
            acc2[2][2]=ffma2(x2,w2,acc2[2][2]); acc2[2][3]=ffma2(x2,w3,acc2[2][3]);
            acc2[3][0]=ffma2(x3,w0,acc2[3][0]); acc2[3][1]=ffma2(x3,w1,acc2[3][1]);
            acc2[3][2]=ffma2(x3,w2,acc2[3][2]); acc2[3][3]=ffma2(x3,w3,acc2[3][3]);
        }
    }
    float a[8][4];
    #pragma unroll
    for(int p=0;p<4;p++)
        #pragma unroll
        for(int j=0;j<4;j++) upk2(acc2[p][j],a[2*p][j],a[2*p+1][j]);
    float4 bo=*(const float4*)&bias[o0+tx*4];
    float bb[4]={bo.x,bo.y,bo.z,bo.w};
    if(MODE==0){
        #pragma unroll
        for(int i=0;i<8;i++){
            __align__(8) __half hh[4];
            #pragma unroll
            for(int j=0;j<4;j++) hh[j]=__float2half_rn(a[i][j]+bb[j]);
            size_t base=((size_t)(b*N_)+n0+ty*8+i)*CK_+o0+tx*4;
            *(uint2*)&Yh[base]=*(uint2*)hh;
        }
    } else {
        #pragma unroll
        for(int j=0;j<4;j++){
            __align__(16) __half vh[8], wh[8];
            #pragma unroll
            for(int i=0;i<8;i++){
                float y=a[i][j]+bb[j];
                vh[i]=__float2half_rn(y);
                wh[i]=__float2half_rn(y*y);
            }
            int o=o0+tx*4+j;
            size_t rv=((size_t)b*(2*C_)+2*o)*N_+n0+ty*8;
            *(uint4*)&Yh[rv]=*(uint4*)vh; *(uint4*)&Yh[rv+N_]=*(uint4*)wh;
        }
    }
}

// ---------------- kernel 3: S = Q K^T  (mma.sync + ldmatrix, 1-term, 3-stage) ----------------
// CTA 128q x 256k, 8 warps (64x64). Chunk = 64 ck (7 chunks). Rows padded 144B.
#define SG_Q  0
#define SG_KH 18432
#define SG_STAGE 55296
#define SG_SMEM (3*SG_STAGE)
__global__ __launch_bounds__(256) void sgemm_kernel(){
    extern __shared__ char sm[];
    uint32_t sb = smem_to_u32(sm);
    int tid=threadIdx.x, lane=tid&31, wid=tid>>5;
    int g=lane>>2, tig=lane&3;
    int wq=wid&1, wk=wid>>1;
    int lrow=lane&15, lcol=lane>>4;
    int b=blockIdx.z, q0=blockIdx.y*128, k0=blockIdx.x*256;
    const __half* Qg=g_Qh+((size_t)b*N_+q0)*CK_;
    const __half* Khg=g_Kh+((size_t)b*N_+k0)*CK_;

    auto issue=[&](int ch, int st){
        uint32_t base = sb + st*SG_STAGE;
        int ck0=ch*64;
        for(int i=tid;i<1024;i+=256){
            int r=i>>3, s=i&7;
            cp16(base+SG_Q + r*144 + s*16, Qg + (size_t)r*CK_ + ck0 + s*8);
        }
        for(int i=tid;i<2048;i+=256){
            int r=i>>3, s=i&7;
            cp16(base+SG_KH + r*144 + s*16, Khg + (size_t)r*CK_ + ck0 + s*8);
        }
    };

    float acc[4][8][4];
    #pragma unroll
    for(int mi=0;mi<4;mi++)
        #pragma unroll
        for(int ni=0;ni<8;ni++)
            #pragma unroll
            for(int e=0;e<4;e++) acc[mi][ni][e]=0.f;

    issue(0,0); CP_COMMIT();
    issue(1,1); CP_COMMIT();
    int st=2;
    for(int ch=0; ch<7; ch++){
        if(ch+2<7){ issue(ch+2,st); CP_COMMIT(); st=(st+1==3)?0:st+1; CP_WAIT2(); }
        else if(ch+1<7){ CP_WAIT1(); }
        else { CP_WAIT0(); }
        __syncthreads();
        uint32_t stg = sb + (ch%3)*SG_STAGE;
        #pragma unroll
        for(int ks=0;ks<4;ks++){
            int kbo = (ks*16 + lcol*8)*2;
            uint32_t bh[8][2];
            #pragma unroll
            for(int nb=0;nb<4;nb++){
                uint32_t r4[4];
                ldm4(r4, stg+SG_KH + (wk*64+nb*16+lrow)*144 + kbo);
                bh[2*nb][0]=r4[0]; bh[2*nb+1][0]=r4[1]; bh[2*nb][1]=r4[2]; bh[2*nb+1][1]=r4[3];
            }
            #pragma unroll
            for(int mi=0;mi<4;mi++){
                uint32_t a[4];
                ldm4(a, stg+SG_Q + (wq*64+mi*16+lrow)*144 + kbo);
                #pragma unroll
                for(int ni=0;ni<8;ni++) mma16816(acc[mi][ni], a, bh[ni]);
            }
        }
        __syncthreads();
    }
    float* So = g_S + ((size_t)b*N_+q0)*N_ + k0;
    #pragma unroll
    for(int mi=0;mi<4;mi++){
        int qr=wq*64+mi*16+g;
        #pragma unroll
        for(int ni=0;ni<8;ni++){
            int kc=wk*64+ni*8+tig*2;
            float2 v0={acc[mi][ni][0],acc[mi][ni][1]};
            float2 v1={acc[mi][ni][2],acc[mi][ni][3]};
            *(float2*)&So[(size_t)qr*N_+kc]     = v0;
            *(float2*)&So[(size_t)(qr+8)*N_+kc] = v1;
        }
    }
}

// ---------------- kernel 4: masked softmax row pass ----------------
__global__ __launch_bounds__(256) void softmax_kernel(const int* __restrict__ cmask,
                                                      const int* __restrict__ smask){
    int b=blockIdx.y, q=blockIdx.x, tid=threadIdx.x;
    const float4* Srow=(const float4*)(g_S+((size_t)b*N_+q)*N_);
    const int4* smr=(const int4*)(smask+b*N_);
    int cm = cmask[b*N_+q]!=0;
    float s[16], mx=-3.4e38f;
    #pragma unroll
    for(int i=0;i<4;i++){
        int k4=tid+i*256;
        float4 v=Srow[k4];
        if(cm){
            int4 m=smr[k4];
            if(m.x==0)v.x=NEGV; if(m.y==0)v.y=NEGV; if(m.z==0)v.z=NEGV; if(m.w==0)v.w=NEGV;
        }
        s[4*i]=v.x;s[4*i+1]=v.y;s[4*i+2]=v.z;s[4*i+3]=v.w;
        mx=fmaxf(mx,fmaxf(fmaxf(v.x,v.y),fmaxf(v.z,v.w)));
    }
    #pragma unroll
    for(int o=16;o;o>>=1) mx=fmaxf(mx,__shfl_xor_sync(~0u,mx,o));
    __shared__ float red[8];
    int w=tid>>5,l=tid&31;
    if(l==0) red[w]=mx;
    __syncthreads();
    float M=red[0];
    #pragma unroll
    for(int i=1;i<8;i++) M=fmaxf(M,red[i]);
    __syncthreads();
    float sum=0.f;
    uint2* Prow=(uint2*)(g_P+((size_t)b*N_+q)*N_);
    #pragma unroll
    for(int i=0;i<4;i++){
        __align__(8) __half h[4];
        #pragma unroll
        for(int j=0;j<4;j++){
            float p=fast_exp(s[4*i+j]-M);
            h[j]=__float2half_rn(p);
            sum+=__half2float(h[j]);
        }
        Prow[tid+i*256]=*(uint2*)h;
    }
    #pragma unroll
    for(int o=16;o;o>>=1) sum+=__shfl_xor_sync(~0u,sum,o);
    if(l==0) red[w]=sum;
    __syncthreads();
    if(tid==0){
        float t=0.f;
        #pragma unroll
        for(int i=0;i<8;i++) t+=red[i];
        g_l[b*N_+q]=t;
    }
}

// ---------------- kernel 5: [mean,m2] = P * VT^T (mma.sync + ldmatrix, 1-term) ----------------
// CTA 128q x 256j, 8 warps 64x64. Chunk 64 keys (64 chunks), 3 stages.
#define PV_P 0
#define PV_V 18432
#define PV_STAGE 55296
#define PV_SMEM (3*PV_STAGE)
__global__ __launch_bounds__(256) void pv_kernel(){
    extern __shared__ char sm[];
    uint32_t sb = smem_to_u32(sm);
    int tid=threadIdx.x, lane=tid&31, wid=tid>>5;
    int g=lane>>2, tig=lane&3;
    int wq=wid&1, wk=wid>>1;
    int lrow=lane&15, lcol=lane>>4;
    int b=blockIdx.z, q0=blockIdx.y*128, j0=blockIdx.x*256;
    const __half* Pg = g_P  + ((size_t)b*N_+q0)*N_;
    const __half* Vg = g_VTh+ ((size_t)b*2*C_+j0)*N_;

    auto issue=[&](int ch, int st){
        uint32_t base = sb + st*PV_STAGE;
        int kk0=ch*64;
        for(int i=tid;i<1024;i+=256){
            int r=i>>3, s=i&7;
            cp16(base+PV_P + r*144 + s*16, Pg + (size_t)r*N_ + kk0 + s*8);
        }
        for(int i=tid;i<2048;i+=256){
            int r=i>>3, s=i&7;
            cp16(base+PV_V + r*144 + s*16, Vg + (size_t)r*N_ + kk0 + s*8);
        }
    };

    float acc[4][8][4];
    #pragma unroll
    for(int mi=0;mi<4;mi++)
        #pragma unroll
        for(int ni=0;ni<8;ni++)
            #pragma unroll
            for(int e=0;e<4;e++) acc[mi][ni][e]=0.f;

    issue(0,0); CP_COMMIT();
    issue(1,1); CP_COMMIT();
    int st=2;
    for(int ch=0; ch<64; ch++){
        if(ch+2<64){ issue(ch+2,st); CP_COMMIT(); st=(st+1==3)?0:st+1; CP_WAIT2(); }
        else if(ch+1<64){ CP_WAIT1(); }
        else { CP_WAIT0(); }
        __syncthreads();
        uint32_t stg = sb + (ch%3)*PV_STAGE;
        #pragma unroll
        for(int ks=0;ks<4;ks++){
            int kbo = (ks*16 + lcol*8)*2;
            uint32_t bh[8][2];
            #pragma unroll
            for(int nb=0;nb<4;nb++){
                uint32_t r4[4];
                ldm4(r4, stg+PV_V + (wk*64+nb*16+lrow)*144 + kbo);
                bh[2*nb][0]=r4[0]; bh[2*nb+1][0]=r4[1]; bh[2*nb][1]=r4[2]; bh[2*nb+1][1]=r4[3];
            }
            #pragma unroll
            for(int mi=0;mi<4;mi++){
                uint32_t a[4];
                ldm4(a, stg+PV_P + (wq*64+mi*16+lrow)*144 + kbo);
                #pragma unroll
                for(int ni=0;ni<8;ni++) mma16816(acc[mi][ni], a, bh[ni]);
            }
        }
        __syncthreads();
    }
    float* Ob = g_O + ((size_t)b*N_+q0)*(2*C_) + j0;
    #pragma unroll
    for(int mi=0;mi<4;mi++){
        int qr=wq*64+mi*16+g;
        #pragma unroll
        for(int ni=0;ni<8;ni++){
            int jc=wk*64+ni*8+tig*2;
            float2 v0={acc[mi][ni][0],acc[mi][ni][1]};
            float2 v1={acc[mi][ni][2],acc[mi][ni][3]};
            *(float2*)&Ob[(size_t)qr*(2*C_)+jc]     = v0;
            *(float2*)&Ob[(size_t)(qr+8)*(2*C_)+jc] = v1;
        }
    }
}

// ---------------- kernel 6: finalize ----------------
__global__ __launch_bounds__(256) void final_kernel(const float* __restrict__ content,
                                                    float* __restrict__ out){
    int b=blockIdx.z, c=blockIdx.y;
    int n=(blockIdx.x*256+threadIdx.x)*4;
    const float* Ob=g_O+(size_t)b*N_*(2*C_);
    float4 l4=*(const float4*)&g_l[b*N_+n];
    float lv[4]={l4.x,l4.y,l4.z,l4.w};
    float cmv=g_cmean[b*C_+c], cr=g_crstd[b*C_+c];
    size_t oi=((size_t)(b*C_+c))*N_+n;
    float4 cx=*(const float4*)&content[oi];
    float ci[4]={cx.x,cx.y,cx.z,cx.w};
    float res[4];
    #pragma unroll
    for(int i=0;i<4;i++){
        float2 mv=*(const float2*)&Ob[(size_t)(n+i)*(2*C_)+2*c];
        float inv=1.0f/lv[i];
        float mean=mv.x*inv, m2=mv.y*inv;
        float sd=sqrtf(fmaxf(m2-mean*mean,0.f));
        res[i]=sd*(ci[i]-cmv)*cr+mean;
    }
    float4 ro={res[0],res[1],res[2],res[3]};
    *(float4*)&out[oi]=ro;
}

// ---------------- launch ----------------
extern "C" void kernel_launch(void* const* d_in, const int* in_sizes, int n_in,
                              void* d_out, int out_size){
    const float* content     = (const float*)d_in[0];
    const float* style       = (const float*)d_in[1];
    const float* content_key = (const float*)d_in[2];
    const float* style_key   = (const float*)d_in[3];
    const int*   cmask       = (const int*)d_in[4];
    const int*   smask       = (const int*)d_in[5];
    const float* Wf=(const float*)d_in[6];  const float* bf=(const float*)d_in[7];
    const float* Wg=(const float*)d_in[8];  const float* bg=(const float*)d_in[9];
    const float* Wh=(const float*)d_in[10]; const float* bh=(const float*)d_in[11];
    float* out=(float*)d_out;

    __half *qh,*kh,*vth;
    cudaGetSymbolAddress((void**)&qh,  g_Qh);
    cudaGetSymbolAddress((void**)&kh,  g_Kh);
    cudaGetSymbolAddress((void**)&vth, g_VTh);
    cudaFuncSetAttribute(sgemm_kernel, cudaFuncAttributeMaxDynamicSharedMemorySize, SG_SMEM);
    cudaFuncSetAttribute(pv_kernel,    cudaFuncAttributeMaxDynamicSharedMemorySize, PV_SMEM);

    stats_kernel<<<B_*C_, 256>>>(content);
    proj_kernel<CK_,0><<<dim3(32, 7, B_), 256>>>(content_key, Wf, bf, qh);
    proj_kernel<CK_,0><<<dim3(32, 7, B_), 256>>>(style_key,   Wg, bg, kh);
    proj_kernel<C_, 1><<<dim3(32, 4, B_), 256>>>(style,       Wh, bh, vth);
    sgemm_kernel<<<dim3(16, 32, B_), 256, SG_SMEM>>>();
    softmax_kernel<<<dim3(N_, B_), 256>>>(cmask, smask);
    pv_kernel<<<dim3(2, 32, B_), 256, PV_SMEM>>>();
    final_kernel<<<dim3(4, C_, B_), 256>>>(content, out);
}